// round 7
// baseline (speedup 1.0000x reference)
#include <cuda_runtime.h>
#include <math.h>

// ---------------------------------------------------------------------------
// Problem constants
// ---------------------------------------------------------------------------
#define BB   4      // batch
#define CC   64     // C
#define EE   128    // E = 2C
#define HH   128
#define WWID 128
#define WS_  8
#define STR_ 4
#define NH_  31     // windows per dim
#define NWIN (NH_*NH_)          // 961
#define NWB  (NWIN*BB)          // 3844
#define NTOK (NWB*64)           // 246016 token rows
#define HW   (HH*WWID)          // 16384

// ---------------------------------------------------------------------------
// Scratch (static device globals; no runtime allocation)
// ---------------------------------------------------------------------------
__device__ __align__(16) float g_mid [BB*64*HW];          // conv1 out (mag ch0..31, ang ch32..63)
__device__ __align__(16) float g_nhwc[BB*HW*EE];           // combined0, NHWC
__device__ __align__(16) float g_x   [(size_t)NTOK*128];   // tokens
__device__ __align__(16) float g_qkv [(size_t)NTOK*384];
__device__ __align__(16) float g_o2  [(size_t)NTOK*128];
__device__ __align__(16) float g_att [(size_t)NTOK*128];

// ---------------------------------------------------------------------------
// conv1: 3x3, 64 -> 32 per branch, ReLU.  in = vector_field (branch offset),
// out = g_mid.  Block: 16x16 threads, tile 16h x 32w, 8 oc per block,
// 2 pixels per thread.
// ---------------------------------------------------------------------------
__global__ void conv1_kernel(const float* __restrict__ vf,
                             const float* __restrict__ mw1, const float* __restrict__ mb1,
                             const float* __restrict__ aw1, const float* __restrict__ ab1)
{
    int z   = blockIdx.z;            // b*8 + br*4 + ocg
    int b   = z >> 3;
    int br  = (z >> 2) & 1;
    int ocg = z & 3;
    const float* w    = br ? aw1 : mw1;   // [32][64][9]
    const float* bias = br ? ab1 : mb1;
    int ocBase = ocg * 8;
    int x0 = blockIdx.x * 32, y0 = blockIdx.y * 16;
    int tx = threadIdx.x, ty = threadIdx.y;
    int tid = ty * 16 + tx;

    __shared__ float sh[8][18][35];
    __shared__ float wsh[8][8][9];

    float acc[8][2];
#pragma unroll
    for (int o = 0; o < 8; o++) {
        float bv = bias[ocBase + o];
        acc[o][0] = bv; acc[o][1] = bv;
    }

    const float* inBase = vf + (size_t)(b * 128 + br * 64) * HW;

    for (int ic0 = 0; ic0 < 64; ic0 += 8) {
        __syncthreads();
        // stage input halo 8 x 18 x 34
        for (int idx = tid; idx < 8 * 18 * 34; idx += 256) {
            int ic = idx / (18 * 34);
            int r  = idx % (18 * 34);
            int iy = r / 34, ix = r % 34;
            int gy = y0 + iy - 1, gx = x0 + ix - 1;
            float v = 0.f;
            if (gy >= 0 && gy < HH && gx >= 0 && gx < WWID)
                v = inBase[(size_t)(ic0 + ic) * HW + gy * WWID + gx];
            sh[ic][iy][ix] = v;
        }
        // stage weights 8oc x 8ic x 9
        for (int idx = tid; idx < 8 * 8 * 9; idx += 256) {
            int o = idx / 72;
            int r = idx % 72;
            int ic = r / 9, k = r % 9;
            wsh[o][ic][k] = w[(ocBase + o) * 576 + (ic0 + ic) * 9 + k];
        }
        __syncthreads();
#pragma unroll
        for (int ic = 0; ic < 8; ic++) {
#pragma unroll
            for (int ky = 0; ky < 3; ky++) {
                float xv[4];
#pragma unroll
                for (int q = 0; q < 4; q++) xv[q] = sh[ic][ty + ky][tx * 2 + q];
#pragma unroll
                for (int kx = 0; kx < 3; kx++) {
#pragma unroll
                    for (int o = 0; o < 8; o++) {
                        float wv = wsh[o][ic][ky * 3 + kx];
                        acc[o][0] += xv[kx]     * wv;
                        acc[o][1] += xv[kx + 1] * wv;
                    }
                }
            }
        }
    }
    int y = y0 + ty, x = x0 + tx * 2;
#pragma unroll
    for (int o = 0; o < 8; o++) {
        float* p = g_mid + (size_t)(b * 64 + br * 32 + ocBase + o) * HW + y * WWID + x;
        p[0] = fmaxf(acc[o][0], 0.f);
        p[1] = fmaxf(acc[o][1], 0.f);
    }
}

// ---------------------------------------------------------------------------
// conv2: 3x3, 32 -> 64 per branch, no ReLU, writes NHWC combined0.
// ---------------------------------------------------------------------------
__global__ void conv2_kernel(const float* __restrict__ mw2, const float* __restrict__ mb2,
                             const float* __restrict__ aw2, const float* __restrict__ ab2)
{
    int z   = blockIdx.z;            // b*16 + br*8 + ocg
    int b   = z >> 4;
    int br  = (z >> 3) & 1;
    int ocg = z & 7;
    const float* w    = br ? aw2 : mw2;   // [64][32][9]
    const float* bias = br ? ab2 : mb2;
    int ocBase = ocg * 8;
    int x0 = blockIdx.x * 32, y0 = blockIdx.y * 16;
    int tx = threadIdx.x, ty = threadIdx.y;
    int tid = ty * 16 + tx;

    __shared__ float sh[8][18][35];
    __shared__ float wsh[8][8][9];

    float acc[8][2];
#pragma unroll
    for (int o = 0; o < 8; o++) {
        float bv = bias[ocBase + o];
        acc[o][0] = bv; acc[o][1] = bv;
    }

    const float* inBase = g_mid + (size_t)(b * 64 + br * 32) * HW;

    for (int ic0 = 0; ic0 < 32; ic0 += 8) {
        __syncthreads();
        for (int idx = tid; idx < 8 * 18 * 34; idx += 256) {
            int ic = idx / (18 * 34);
            int r  = idx % (18 * 34);
            int iy = r / 34, ix = r % 34;
            int gy = y0 + iy - 1, gx = x0 + ix - 1;
            float v = 0.f;
            if (gy >= 0 && gy < HH && gx >= 0 && gx < WWID)
                v = inBase[(size_t)(ic0 + ic) * HW + gy * WWID + gx];
            sh[ic][iy][ix] = v;
        }
        for (int idx = tid; idx < 8 * 8 * 9; idx += 256) {
            int o = idx / 72;
            int r = idx % 72;
            int ic = r / 9, k = r % 9;
            wsh[o][ic][k] = w[(ocBase + o) * 288 + (ic0 + ic) * 9 + k];
        }
        __syncthreads();
#pragma unroll
        for (int ic = 0; ic < 8; ic++) {
#pragma unroll
            for (int ky = 0; ky < 3; ky++) {
                float xv[4];
#pragma unroll
                for (int q = 0; q < 4; q++) xv[q] = sh[ic][ty + ky][tx * 2 + q];
#pragma unroll
                for (int kx = 0; kx < 3; kx++) {
#pragma unroll
                    for (int o = 0; o < 8; o++) {
                        float wv = wsh[o][ic][ky * 3 + kx];
                        acc[o][0] += xv[kx]     * wv;
                        acc[o][1] += xv[kx + 1] * wv;
                    }
                }
            }
        }
    }
    int y = y0 + ty, x = x0 + tx * 2;
    int e0 = br * 64 + ocBase;
#pragma unroll
    for (int px = 0; px < 2; px++) {
        float4 f0 = make_float4(acc[0][px], acc[1][px], acc[2][px], acc[3][px]);
        float4 f1 = make_float4(acc[4][px], acc[5][px], acc[6][px], acc[7][px]);
        float* p = g_nhwc + ((size_t)(b * HH + y) * WWID + (x + px)) * EE + e0;
        reinterpret_cast<float4*>(p)[0] = f0;
        reinterpret_cast<float4*>(p)[1] = f1;
    }
}

// ---------------------------------------------------------------------------
// Token gather: X[row][e] from NHWC combined0.  row = (win*4+b)*64 + r*8+c.
// ---------------------------------------------------------------------------
__global__ void gather_kernel()
{
    int idx = blockIdx.x * blockDim.x + threadIdx.x;   // float4 index
    if (idx >= NTOK * 32) return;
    int e4  = idx & 31;
    int row = idx >> 5;
    int l   = row & 63;
    int wb  = row >> 6;
    int b   = wb & 3;
    int win = wb >> 2;
    int hi = win / NH_, wi = win % NH_;
    int h = hi * 4 + (l >> 3);
    int wc = wi * 4 + (l & 7);
    const float4* src = reinterpret_cast<const float4*>(
        g_nhwc + ((size_t)(b * HH + h) * WWID + wc) * EE) + e4;
    reinterpret_cast<float4*>(g_x)[(size_t)row * 32 + e4] = *src;
}

// ---------------------------------------------------------------------------
// Generic GEMM: C[M x N] = A[M x 128] * Wt[N x 128]^T + bias.
// BM=128, BN=64, BK=16; 256 threads; 8x4 per-thread register tile.
// ---------------------------------------------------------------------------
__global__ void gemm_kernel(const float* __restrict__ A, const float* __restrict__ Wt,
                            const float* __restrict__ bias, float* __restrict__ C, int N)
{
    __shared__ float As[16][132];
    __shared__ float Bs[16][68];
    int tid = threadIdx.x;
    int mt = tid >> 4, nt = tid & 15;
    int m0 = blockIdx.y * 128;
    int n0 = blockIdx.x * 64;

    float acc[8][4];
#pragma unroll
    for (int i = 0; i < 8; i++)
#pragma unroll
        for (int j = 0; j < 4; j++) acc[i][j] = 0.f;

    for (int k0 = 0; k0 < 128; k0 += 16) {
#pragma unroll
        for (int s = 0; s < 2; s++) {
            int id = tid + s * 256;
            int r = id >> 2, q = id & 3;
            float4 v = *reinterpret_cast<const float4*>(A + (size_t)(m0 + r) * 128 + k0 + q * 4);
            As[q * 4 + 0][r] = v.x; As[q * 4 + 1][r] = v.y;
            As[q * 4 + 2][r] = v.z; As[q * 4 + 3][r] = v.w;
        }
        {
            int r = tid >> 2, q = tid & 3;
            float4 v = *reinterpret_cast<const float4*>(Wt + (size_t)(n0 + r) * 128 + k0 + q * 4);
            Bs[q * 4 + 0][r] = v.x; Bs[q * 4 + 1][r] = v.y;
            Bs[q * 4 + 2][r] = v.z; Bs[q * 4 + 3][r] = v.w;
        }
        __syncthreads();
#pragma unroll
        for (int k = 0; k < 16; k++) {
            float a[8], bb[4];
#pragma unroll
            for (int i = 0; i < 8; i++) a[i] = As[k][mt + 16 * i];
#pragma unroll
            for (int j = 0; j < 4; j++) bb[j] = Bs[k][nt + 16 * j];
#pragma unroll
            for (int i = 0; i < 8; i++)
#pragma unroll
                for (int j = 0; j < 4; j++) acc[i][j] += a[i] * bb[j];
        }
        __syncthreads();
    }
    float bj[4];
#pragma unroll
    for (int j = 0; j < 4; j++) bj[j] = __ldg(bias + n0 + nt + 16 * j);
#pragma unroll
    for (int i = 0; i < 8; i++) {
        int m = m0 + mt + 16 * i;
#pragma unroll
        for (int j = 0; j < 4; j++)
            C[(size_t)m * N + n0 + nt + 16 * j] = acc[i][j] + bj[j];
    }
}

// ---------------------------------------------------------------------------
// Attention core: one block per (window*batch, head).
// softmax(q k^T / sqrt(hd)) v  for L=64, hd=32.
// ---------------------------------------------------------------------------
__global__ void attn_kernel()
{
    __shared__ float qs[64][33];
    __shared__ float ks[64][33];
    __shared__ float vs[64][33];
    __shared__ float st[64][65];

    int bx = blockIdx.x;
    int head = bx & 3;
    int wb   = bx >> 2;
    int rowBase = wb * 64;
    int tid = threadIdx.x;
    const float scale = 0.17677669529663687f;  // 1/sqrt(32)

    for (int idx = tid; idx < 64 * 32; idx += 256) {
        int l = idx >> 5, d = idx & 31;
        const float* p = g_qkv + (size_t)(rowBase + l) * 384 + head * 32 + d;
        qs[l][d] = p[0] * scale;
        ks[l][d] = p[128];
        vs[l][d] = p[256];
    }
    __syncthreads();

    // scores: st[m? no: st[l][m]] ; thread (lt, mt), tile 4l x 4m
    {
        int mt = tid & 15, lt = tid >> 4;
        float acc[4][4];
#pragma unroll
        for (int i = 0; i < 4; i++)
#pragma unroll
            for (int j = 0; j < 4; j++) acc[i][j] = 0.f;
#pragma unroll
        for (int d = 0; d < 32; d++) {
            float a[4], bb[4];
#pragma unroll
            for (int i = 0; i < 4; i++) a[i] = qs[lt * 4 + i][d];
#pragma unroll
            for (int j = 0; j < 4; j++) bb[j] = ks[mt + 16 * j][d];
#pragma unroll
            for (int i = 0; i < 4; i++)
#pragma unroll
                for (int j = 0; j < 4; j++) acc[i][j] += a[i] * bb[j];
        }
#pragma unroll
        for (int i = 0; i < 4; i++)
#pragma unroll
            for (int j = 0; j < 4; j++) st[lt * 4 + i][mt + 16 * j] = acc[i][j];
    }
    __syncthreads();

    // softmax over m per row l (64 rows, one thread each)
    if (tid < 64) {
        float mx = -1e30f;
#pragma unroll 8
        for (int m = 0; m < 64; m++) mx = fmaxf(mx, st[tid][m]);
        float s = 0.f;
#pragma unroll 8
        for (int m = 0; m < 64; m++) {
            float e = expf(st[tid][m] - mx);
            st[tid][m] = e;
            s += e;
        }
        float inv = 1.f / s;
#pragma unroll 8
        for (int m = 0; m < 64; m++) st[tid][m] *= inv;
    }
    __syncthreads();

    // AV: out [64 x 32], thread (lt, dt), tile 4l x 2d
    {
        int dt = tid & 15, lt = tid >> 4;
        float acc[4][2];
#pragma unroll
        for (int i = 0; i < 4; i++) { acc[i][0] = 0.f; acc[i][1] = 0.f; }
#pragma unroll 4
        for (int m = 0; m < 64; m++) {
            float a[4];
#pragma unroll
            for (int i = 0; i < 4; i++) a[i] = st[lt * 4 + i][m];
            float b0 = vs[m][dt], b1 = vs[m][dt + 16];
#pragma unroll
            for (int i = 0; i < 4; i++) {
                acc[i][0] += a[i] * b0;
                acc[i][1] += a[i] * b1;
            }
        }
#pragma unroll
        for (int i = 0; i < 4; i++) {
            int l = lt * 4 + i;
            g_o2[(size_t)(rowBase + l) * 128 + head * 32 + dt]      = acc[i][0];
            g_o2[(size_t)(rowBase + l) * 128 + head * 32 + dt + 16] = acc[i][1];
        }
    }
}

// ---------------------------------------------------------------------------
// Blend (analytic scan) + 1x1 conv + sigmoid gate + residual, coalesced NCHW out.
// Block: 256 threads, tile = 32 pixels along w for one (b, h).
// ---------------------------------------------------------------------------
__global__ void blend_kernel(const float* __restrict__ fcw, const float* __restrict__ fcb,
                             const float* __restrict__ vf, float* __restrict__ out)
{
    __shared__ float enh[32][129];
    __shared__ float fw [32][65];

    int wc = blockIdx.x;     // 0..3
    int h  = blockIdx.y;     // 0..127
    int b  = blockIdx.z;     // 0..3
    int w0 = wc * 32;
    int tid = threadIdx.x;

    int hiLo = max(0, (h - 4) >> 2);
    int hiHi = min(NH_ - 1, h >> 2);

    // Phase 1: enhanced = sequential-scan-equivalent fold per pixel
    for (int s = 0; s < 16; s++) {
        int idx = tid + s * 256;
        int px = idx >> 7;
        int e  = idx & 127;
        int wpix = w0 + px;
        int wiLo = max(0, (wpix - 4) >> 2);
        int wiHi = min(NH_ - 1, wpix >> 2);

        float val = g_nhwc[((size_t)(b * HH + h) * WWID + wpix) * EE + e];
        for (int hi = hiLo; hi <= hiHi; hi++) {
            int lr = (h - hi * 4) * 8;
            for (int wi = wiLo; wi <= wiHi; wi++) {
                int l = lr + (wpix - wi * 4);
                int row = ((hi * NH_ + wi) * 4 + b) * 64 + l;
                val = val * 0.7f + 0.3f * g_att[(size_t)row * 128 + e];
            }
        }
        enh[px][e] = val;
    }
    __syncthreads();

    // Phase 2: flow weights = sigmoid(fc_w @ enh + fc_b)
    for (int s = 0; s < 8; s++) {
        int idx = tid + s * 256;
        int px = idx >> 6;
        int c  = idx & 63;
        float sum = __ldg(fcb + c);
        const float* wr = fcw + c * 128;
#pragma unroll 8
        for (int e = 0; e < 128; e++) sum += __ldg(wr + e) * enh[px][e];
        fw[px][c] = 1.f / (1.f + expf(-sum));
    }
    __syncthreads();

    // Phase 3: out (NCHW) = enh * fw(gate) + vf   (coalesced along w)
    for (int s = 0; s < 16; s++) {
        int idx = tid + s * 256;
        int px = idx & 31;
        int ch = idx >> 5;
        size_t off = ((size_t)(b * 128 + ch) * HH + h) * WWID + w0 + px;
        out[off] = enh[px][ch] * fw[px][ch & 63] + vf[off];
    }
}

// ---------------------------------------------------------------------------
// Launch
// ---------------------------------------------------------------------------
extern "C" void kernel_launch(void* const* d_in, const int* in_sizes, int n_in,
                              void* d_out, int out_size)
{
    const float* vf    = (const float*)d_in[0];
    const float* mw1   = (const float*)d_in[1];
    const float* mb1   = (const float*)d_in[2];
    const float* mw2   = (const float*)d_in[3];
    const float* mb2   = (const float*)d_in[4];
    const float* aw1   = (const float*)d_in[5];
    const float* ab1   = (const float*)d_in[6];
    const float* aw2   = (const float*)d_in[7];
    const float* ab2   = (const float*)d_in[8];
    const float* ipw   = (const float*)d_in[9];   // [384,128]
    const float* ipb   = (const float*)d_in[10];
    const float* opw   = (const float*)d_in[11];  // [128,128]
    const float* opb   = (const float*)d_in[12];
    const float* fcw   = (const float*)d_in[13];  // [64,128]
    const float* fcb   = (const float*)d_in[14];
    float* out = (float*)d_out;

    void *px, *pqkv, *po2, *patt;
    cudaGetSymbolAddress(&px,   g_x);
    cudaGetSymbolAddress(&pqkv, g_qkv);
    cudaGetSymbolAddress(&po2,  g_o2);
    cudaGetSymbolAddress(&patt, g_att);

    dim3 cblk(16, 16);
    conv1_kernel<<<dim3(4, 8, 32), cblk>>>(vf, mw1, mb1, aw1, ab1);
    conv2_kernel<<<dim3(4, 8, 64), cblk>>>(mw2, mb2, aw2, ab2);

    gather_kernel<<<(NTOK * 32) / 256, 256>>>();

    // QKV: [NTOK,128] x [384,128]^T
    gemm_kernel<<<dim3(6, NTOK / 128), 256>>>((const float*)px, ipw, ipb, (float*)pqkv, 384);

    attn_kernel<<<NWB * 4, 256>>>();

    // out-proj: [NTOK,128] x [128,128]^T
    gemm_kernel<<<dim3(2, NTOK / 128), 256>>>((const float*)po2, opw, opb, (float*)patt, 128);

    blend_kernel<<<dim3(4, HH, BB), 256>>>(fcw, fcb, vf, out);
}

// round 8
// speedup vs baseline: 1.2035x; 1.2035x over previous
#include <cuda_runtime.h>
#include <math.h>
#include <stdint.h>

// ---------------------------------------------------------------------------
// Problem constants
// ---------------------------------------------------------------------------
#define BB   4      // batch
#define CC   64     // C
#define EE   128    // E = 2C
#define HH   128
#define WWID 128
#define WS_  8
#define STR_ 4
#define NH_  31     // windows per dim
#define NWIN (NH_*NH_)          // 961
#define NWB  (NWIN*BB)          // 3844
#define NTOK (NWB*64)           // 246016 token rows
#define HW   (HH*WWID)          // 16384

// ---------------------------------------------------------------------------
// Scratch (static device globals; no runtime allocation)
// ---------------------------------------------------------------------------
__device__ __align__(16) float g_mid [BB*64*HW];          // conv1 out
__device__ __align__(16) float g_nhwc[BB*HW*EE];           // combined0, NHWC
__device__ __align__(16) float g_qkv [(size_t)NTOK*384];
__device__ __align__(16) float g_o2  [(size_t)NTOK*128];
__device__ __align__(16) float g_att [(size_t)NTOK*128];

// ---------------------------------------------------------------------------
// tf32 helpers
// ---------------------------------------------------------------------------
__device__ __forceinline__ uint32_t f2tf(float f) {
    uint32_t u;
    asm("cvt.rna.tf32.f32 %0, %1;" : "=r"(u) : "f"(f));
    return u;
}

__device__ __forceinline__ void mma_tf32(float* d, const uint32_t* a, const uint32_t* b) {
    asm volatile(
        "mma.sync.aligned.m16n8k8.row.col.f32.tf32.tf32.f32 "
        "{%0,%1,%2,%3}, {%4,%5,%6,%7}, {%8,%9}, {%0,%1,%2,%3};\n"
        : "+f"(d[0]), "+f"(d[1]), "+f"(d[2]), "+f"(d[3])
        : "r"(a[0]), "r"(a[1]), "r"(a[2]), "r"(a[3]), "r"(b[0]), "r"(b[1]));
}

// ---------------------------------------------------------------------------
// conv1: 3x3, 64 -> 32 per branch, ReLU.
// ---------------------------------------------------------------------------
__global__ void conv1_kernel(const float* __restrict__ vf,
                             const float* __restrict__ mw1, const float* __restrict__ mb1,
                             const float* __restrict__ aw1, const float* __restrict__ ab1)
{
    int z   = blockIdx.z;            // b*8 + br*4 + ocg
    int b   = z >> 3;
    int br  = (z >> 2) & 1;
    int ocg = z & 3;
    const float* w    = br ? aw1 : mw1;   // [32][64][9]
    const float* bias = br ? ab1 : mb1;
    int ocBase = ocg * 8;
    int x0 = blockIdx.x * 32, y0 = blockIdx.y * 16;
    int tx = threadIdx.x, ty = threadIdx.y;
    int tid = ty * 16 + tx;

    __shared__ float sh[8][18][35];
    __shared__ float wsh[8][8][9];

    float acc[8][2];
#pragma unroll
    for (int o = 0; o < 8; o++) {
        float bv = bias[ocBase + o];
        acc[o][0] = bv; acc[o][1] = bv;
    }

    const float* inBase = vf + (size_t)(b * 128 + br * 64) * HW;

    for (int ic0 = 0; ic0 < 64; ic0 += 8) {
        __syncthreads();
        for (int idx = tid; idx < 8 * 18 * 34; idx += 256) {
            int ic = idx / (18 * 34);
            int r  = idx % (18 * 34);
            int iy = r / 34, ix = r % 34;
            int gy = y0 + iy - 1, gx = x0 + ix - 1;
            float v = 0.f;
            if (gy >= 0 && gy < HH && gx >= 0 && gx < WWID)
                v = inBase[(size_t)(ic0 + ic) * HW + gy * WWID + gx];
            sh[ic][iy][ix] = v;
        }
        for (int idx = tid; idx < 8 * 8 * 9; idx += 256) {
            int o = idx / 72;
            int r = idx % 72;
            int ic = r / 9, k = r % 9;
            wsh[o][ic][k] = w[(ocBase + o) * 576 + (ic0 + ic) * 9 + k];
        }
        __syncthreads();
#pragma unroll
        for (int ic = 0; ic < 8; ic++) {
#pragma unroll
            for (int ky = 0; ky < 3; ky++) {
                float xv[4];
#pragma unroll
                for (int q = 0; q < 4; q++) xv[q] = sh[ic][ty + ky][tx * 2 + q];
#pragma unroll
                for (int kx = 0; kx < 3; kx++) {
#pragma unroll
                    for (int o = 0; o < 8; o++) {
                        float wv = wsh[o][ic][ky * 3 + kx];
                        acc[o][0] += xv[kx]     * wv;
                        acc[o][1] += xv[kx + 1] * wv;
                    }
                }
            }
        }
    }
    int y = y0 + ty, x = x0 + tx * 2;
#pragma unroll
    for (int o = 0; o < 8; o++) {
        float* p = g_mid + (size_t)(b * 64 + br * 32 + ocBase + o) * HW + y * WWID + x;
        p[0] = fmaxf(acc[o][0], 0.f);
        p[1] = fmaxf(acc[o][1], 0.f);
    }
}

// ---------------------------------------------------------------------------
// conv2: 3x3, 32 -> 64 per branch, no ReLU, writes NHWC combined0.
// ---------------------------------------------------------------------------
__global__ void conv2_kernel(const float* __restrict__ mw2, const float* __restrict__ mb2,
                             const float* __restrict__ aw2, const float* __restrict__ ab2)
{
    int z   = blockIdx.z;            // b*16 + br*8 + ocg
    int b   = z >> 4;
    int br  = (z >> 3) & 1;
    int ocg = z & 7;
    const float* w    = br ? aw2 : mw2;   // [64][32][9]
    const float* bias = br ? ab2 : mb2;
    int ocBase = ocg * 8;
    int x0 = blockIdx.x * 32, y0 = blockIdx.y * 16;
    int tx = threadIdx.x, ty = threadIdx.y;
    int tid = ty * 16 + tx;

    __shared__ float sh[8][18][35];
    __shared__ float wsh[8][8][9];

    float acc[8][2];
#pragma unroll
    for (int o = 0; o < 8; o++) {
        float bv = bias[ocBase + o];
        acc[o][0] = bv; acc[o][1] = bv;
    }

    const float* inBase = g_mid + (size_t)(b * 64 + br * 32) * HW;

    for (int ic0 = 0; ic0 < 32; ic0 += 8) {
        __syncthreads();
        for (int idx = tid; idx < 8 * 18 * 34; idx += 256) {
            int ic = idx / (18 * 34);
            int r  = idx % (18 * 34);
            int iy = r / 34, ix = r % 34;
            int gy = y0 + iy - 1, gx = x0 + ix - 1;
            float v = 0.f;
            if (gy >= 0 && gy < HH && gx >= 0 && gx < WWID)
                v = inBase[(size_t)(ic0 + ic) * HW + gy * WWID + gx];
            sh[ic][iy][ix] = v;
        }
        for (int idx = tid; idx < 8 * 8 * 9; idx += 256) {
            int o = idx / 72;
            int r = idx % 72;
            int ic = r / 9, k = r % 9;
            wsh[o][ic][k] = w[(ocBase + o) * 288 + (ic0 + ic) * 9 + k];
        }
        __syncthreads();
#pragma unroll
        for (int ic = 0; ic < 8; ic++) {
#pragma unroll
            for (int ky = 0; ky < 3; ky++) {
                float xv[4];
#pragma unroll
                for (int q = 0; q < 4; q++) xv[q] = sh[ic][ty + ky][tx * 2 + q];
#pragma unroll
                for (int kx = 0; kx < 3; kx++) {
#pragma unroll
                    for (int o = 0; o < 8; o++) {
                        float wv = wsh[o][ic][ky * 3 + kx];
                        acc[o][0] += xv[kx]     * wv;
                        acc[o][1] += xv[kx + 1] * wv;
                    }
                }
            }
        }
    }
    int y = y0 + ty, x = x0 + tx * 2;
    int e0 = br * 64 + ocBase;
#pragma unroll
    for (int px = 0; px < 2; px++) {
        float4 f0 = make_float4(acc[0][px], acc[1][px], acc[2][px], acc[3][px]);
        float4 f1 = make_float4(acc[4][px], acc[5][px], acc[6][px], acc[7][px]);
        float* p = g_nhwc + ((size_t)(b * HH + y) * WWID + (x + px)) * EE + e0;
        reinterpret_cast<float4*>(p)[0] = f0;
        reinterpret_cast<float4*>(p)[1] = f1;
    }
}

// ---------------------------------------------------------------------------
// tf32 tensor-core GEMM: C[M x N] = A[M x 128] * Wt[N x 128]^T + bias.
// BM=128, BN=128, BK=32.  256 threads = 8 warps (2 m x 4 n), warp tile 64x32.
// mma.m16n8k8: per warp 4 m-tiles x 4 n-tiles.
// GATHER=true: A rows gathered from NHWC combined0 (token rows contiguous).
// ---------------------------------------------------------------------------
template<bool GATHER>
__global__ __launch_bounds__(256)
void gemm_tf32_kernel(const float* __restrict__ A, const float* __restrict__ Wt,
                      const float* __restrict__ bias, float* __restrict__ C, int N)
{
    // pad 136 words: bank = (8k + m) % 32 -> conflict-free fragment loads
    __shared__ uint32_t As[32][136];
    __shared__ uint32_t Bs[32][136];

    int tid  = threadIdx.x;
    int lane = tid & 31;
    int wid  = tid >> 5;
    int wm = wid & 1;        // 0..1  (64 rows each)
    int wn = wid >> 1;       // 0..3  (32 cols each)
    int m0 = blockIdx.y * 128;
    int n0 = blockIdx.x * 128;

    float acc[4][4][4];
#pragma unroll
    for (int mt = 0; mt < 4; mt++)
#pragma unroll
        for (int nt = 0; nt < 4; nt++)
#pragma unroll
            for (int r = 0; r < 4; r++) acc[mt][nt][r] = 0.f;

    // staging assignment: thread handles rows (tid>>3)+32s, k-cols q+8c (q=tid&7)
    int q = tid & 7;
    const float* arow[4];
    const float* brow[4];
    int rowIdx[4];
#pragma unroll
    for (int s = 0; s < 4; s++) {
        int row = (tid >> 3) + 32 * s;
        rowIdx[s] = row;
        if (GATHER) {
            int m  = m0 + row;
            int l  = m & 63;
            int wb = m >> 6;
            int b  = wb & 3;
            int win = wb >> 2;
            int hi = win / 31;
            int wi = win - hi * 31;
            int h  = hi * 4 + (l >> 3);
            int wc = wi * 4 + (l & 7);
            arow[s] = g_nhwc + ((size_t)((b * 128 + h) * 128 + wc)) * 128;
        } else {
            arow[s] = A + (size_t)(m0 + row) * 128;
        }
        brow[s] = Wt + (size_t)(n0 + row) * 128;
    }

    for (int k0 = 0; k0 < 128; k0 += 32) {
        __syncthreads();
#pragma unroll
        for (int s = 0; s < 4; s++) {
#pragma unroll
            for (int c = 0; c < 4; c++) {
                int k = q + 8 * c;
                As[k][rowIdx[s]] = f2tf(arow[s][k0 + k]);
                Bs[k][rowIdx[s]] = f2tf(brow[s][k0 + k]);
            }
        }
        __syncthreads();

#pragma unroll
        for (int kk = 0; kk < 4; kk++) {
            int c = lane & 3;
            int g = lane >> 2;
            uint32_t a[4][4], b[4][2];
#pragma unroll
            for (int mt = 0; mt < 4; mt++) {
                int r = wm * 64 + mt * 16 + g;
                a[mt][0] = As[kk * 8 + c    ][r];
                a[mt][1] = As[kk * 8 + c    ][r + 8];
                a[mt][2] = As[kk * 8 + c + 4][r];
                a[mt][3] = As[kk * 8 + c + 4][r + 8];
            }
#pragma unroll
            for (int nt = 0; nt < 4; nt++) {
                int n = wn * 32 + nt * 8 + g;
                b[nt][0] = Bs[kk * 8 + c    ][n];
                b[nt][1] = Bs[kk * 8 + c + 4][n];
            }
#pragma unroll
            for (int mt = 0; mt < 4; mt++)
#pragma unroll
                for (int nt = 0; nt < 4; nt++)
                    mma_tf32(acc[mt][nt], a[mt], b[nt]);
        }
    }

    // epilogue
    int g  = lane >> 2;
    int c2 = (lane & 3) * 2;
#pragma unroll
    for (int mt = 0; mt < 4; mt++) {
        int row = m0 + wm * 64 + mt * 16 + g;
#pragma unroll
        for (int nt = 0; nt < 4; nt++) {
            int col = n0 + wn * 32 + nt * 8 + c2;
            float b0 = __ldg(bias + col);
            float b1 = __ldg(bias + col + 1);
            float2 v0 = make_float2(acc[mt][nt][0] + b0, acc[mt][nt][1] + b1);
            float2 v1 = make_float2(acc[mt][nt][2] + b0, acc[mt][nt][3] + b1);
            *reinterpret_cast<float2*>(C + (size_t)row * N + col)       = v0;
            *reinterpret_cast<float2*>(C + (size_t)(row + 8) * N + col) = v1;
        }
    }
}

// ---------------------------------------------------------------------------
// Attention core: one block per (window*batch, head).
// softmax(q k^T / sqrt(hd)) v  for L=64, hd=32.  Softmax: 4 threads per row.
// ---------------------------------------------------------------------------
__global__ void attn_kernel()
{
    __shared__ float qs[64][33];
    __shared__ float ks[64][33];
    __shared__ float vs[64][33];
    __shared__ float st[64][65];

    int bx = blockIdx.x;
    int head = bx & 3;
    int wb   = bx >> 2;
    int rowBase = wb * 64;
    int tid = threadIdx.x;
    const float scale = 0.17677669529663687f;  // 1/sqrt(32)

    for (int idx = tid; idx < 64 * 32; idx += 256) {
        int l = idx >> 5, d = idx & 31;
        const float* p = g_qkv + (size_t)(rowBase + l) * 384 + head * 32 + d;
        qs[l][d] = p[0] * scale;
        ks[l][d] = p[128];
        vs[l][d] = p[256];
    }
    __syncthreads();

    // scores st[l][m]; thread (lt, mt), tile 4l x 4m
    {
        int mt = tid & 15, lt = tid >> 4;
        float acc[4][4];
#pragma unroll
        for (int i = 0; i < 4; i++)
#pragma unroll
            for (int j = 0; j < 4; j++) acc[i][j] = 0.f;
#pragma unroll
        for (int d = 0; d < 32; d++) {
            float a[4], bb[4];
#pragma unroll
            for (int i = 0; i < 4; i++) a[i] = qs[lt * 4 + i][d];
#pragma unroll
            for (int j = 0; j < 4; j++) bb[j] = ks[mt + 16 * j][d];
#pragma unroll
            for (int i = 0; i < 4; i++)
#pragma unroll
                for (int j = 0; j < 4; j++) acc[i][j] += a[i] * bb[j];
        }
#pragma unroll
        for (int i = 0; i < 4; i++)
#pragma unroll
            for (int j = 0; j < 4; j++) st[lt * 4 + i][mt + 16 * j] = acc[i][j];
    }
    __syncthreads();

    // softmax over m per row l: 4 threads per row (256 threads = 64 rows x 4)
    {
        int row  = tid >> 2;
        int part = tid & 3;
        float mx = -1e30f;
#pragma unroll
        for (int i = 0; i < 16; i++) mx = fmaxf(mx, st[row][part * 16 + i]);
        mx = fmaxf(mx, __shfl_xor_sync(0xffffffffu, mx, 1));
        mx = fmaxf(mx, __shfl_xor_sync(0xffffffffu, mx, 2));
        float s = 0.f;
        float ev[16];
#pragma unroll
        for (int i = 0; i < 16; i++) {
            float e = __expf(st[row][part * 16 + i] - mx);
            ev[i] = e;
            s += e;
        }
        s += __shfl_xor_sync(0xffffffffu, s, 1);
        s += __shfl_xor_sync(0xffffffffu, s, 2);
        float inv = 1.f / s;
#pragma unroll
        for (int i = 0; i < 16; i++) st[row][part * 16 + i] = ev[i] * inv;
    }
    __syncthreads();

    // AV: out [64 x 32], thread (lt, dt), tile 4l x 2d
    {
        int dt = tid & 15, lt = tid >> 4;
        float acc[4][2];
#pragma unroll
        for (int i = 0; i < 4; i++) { acc[i][0] = 0.f; acc[i][1] = 0.f; }
#pragma unroll 4
        for (int m = 0; m < 64; m++) {
            float a[4];
#pragma unroll
            for (int i = 0; i < 4; i++) a[i] = st[lt * 4 + i][m];
            float b0 = vs[m][dt], b1 = vs[m][dt + 16];
#pragma unroll
            for (int i = 0; i < 4; i++) {
                acc[i][0] += a[i] * b0;
                acc[i][1] += a[i] * b1;
            }
        }
#pragma unroll
        for (int i = 0; i < 4; i++) {
            int l = lt * 4 + i;
            g_o2[(size_t)(rowBase + l) * 128 + head * 32 + dt]      = acc[i][0];
            g_o2[(size_t)(rowBase + l) * 128 + head * 32 + dt + 16] = acc[i][1];
        }
    }
}

// ---------------------------------------------------------------------------
// Blend (analytic scan) + 1x1 conv + sigmoid gate + residual, NCHW out.
// ---------------------------------------------------------------------------
__global__ void blend_kernel(const float* __restrict__ fcw, const float* __restrict__ fcb,
                             const float* __restrict__ vf, float* __restrict__ out)
{
    __shared__ float enh[32][129];
    __shared__ float fw [32][65];

    int wc = blockIdx.x;     // 0..3
    int h  = blockIdx.y;     // 0..127
    int b  = blockIdx.z;     // 0..3
    int w0 = wc * 32;
    int tid = threadIdx.x;

    int hiLo = max(0, (h - 4) >> 2);
    int hiHi = min(NH_ - 1, h >> 2);

    for (int s = 0; s < 16; s++) {
        int idx = tid + s * 256;
        int px = idx >> 7;
        int e  = idx & 127;
        int wpix = w0 + px;
        int wiLo = max(0, (wpix - 4) >> 2);
        int wiHi = min(NH_ - 1, wpix >> 2);

        float val = g_nhwc[((size_t)(b * HH + h) * WWID + wpix) * EE + e];
        for (int hi = hiLo; hi <= hiHi; hi++) {
            int lr = (h - hi * 4) * 8;
            for (int wi = wiLo; wi <= wiHi; wi++) {
                int l = lr + (wpix - wi * 4);
                int row = ((hi * NH_ + wi) * 4 + b) * 64 + l;
                val = val * 0.7f + 0.3f * g_att[(size_t)row * 128 + e];
            }
        }
        enh[px][e] = val;
    }
    __syncthreads();

    for (int s = 0; s < 8; s++) {
        int idx = tid + s * 256;
        int px = idx >> 6;
        int c  = idx & 63;
        float sum = __ldg(fcb + c);
        const float* wr = fcw + c * 128;
#pragma unroll 8
        for (int e = 0; e < 128; e++) sum += __ldg(wr + e) * enh[px][e];
        fw[px][c] = 1.f / (1.f + __expf(-sum));
    }
    __syncthreads();

    for (int s = 0; s < 16; s++) {
        int idx = tid + s * 256;
        int px = idx & 31;
        int ch = idx >> 5;
        size_t off = ((size_t)(b * 128 + ch) * HH + h) * WWID + w0 + px;
        out[off] = enh[px][ch] * fw[px][ch & 63] + vf[off];
    }
}

// ---------------------------------------------------------------------------
// Launch
// ---------------------------------------------------------------------------
extern "C" void kernel_launch(void* const* d_in, const int* in_sizes, int n_in,
                              void* d_out, int out_size)
{
    const float* vf    = (const float*)d_in[0];
    const float* mw1   = (const float*)d_in[1];
    const float* mb1   = (const float*)d_in[2];
    const float* mw2   = (const float*)d_in[3];
    const float* mb2   = (const float*)d_in[4];
    const float* aw1   = (const float*)d_in[5];
    const float* ab1   = (const float*)d_in[6];
    const float* aw2   = (const float*)d_in[7];
    const float* ab2   = (const float*)d_in[8];
    const float* ipw   = (const float*)d_in[9];   // [384,128]
    const float* ipb   = (const float*)d_in[10];
    const float* opw   = (const float*)d_in[11];  // [128,128]
    const float* opb   = (const float*)d_in[12];
    const float* fcw   = (const float*)d_in[13];  // [64,128]
    const float* fcb   = (const float*)d_in[14];
    float* out = (float*)d_out;

    void *pqkv, *po2, *patt;
    cudaGetSymbolAddress(&pqkv, g_qkv);
    cudaGetSymbolAddress(&po2,  g_o2);
    cudaGetSymbolAddress(&patt, g_att);

    dim3 cblk(16, 16);
    conv1_kernel<<<dim3(4, 8, 32), cblk>>>(vf, mw1, mb1, aw1, ab1);
    conv2_kernel<<<dim3(4, 8, 64), cblk>>>(mw2, mb2, aw2, ab2);

    // QKV: tokens (gathered from NHWC) x [384,128]^T  -> g_qkv
    gemm_tf32_kernel<true><<<dim3(3, NTOK / 128), 256>>>(
        nullptr, ipw, ipb, (float*)pqkv, 384);

    attn_kernel<<<NWB * 4, 256>>>();

    // out-proj: g_o2 [NTOK,128] x [128,128]^T -> g_att
    gemm_tf32_kernel<false><<<dim3(1, NTOK / 128), 256>>>(
        (const float*)po2, opw, opb, (float*)patt, 128);

    blend_kernel<<<dim3(4, HH, BB), 256>>>(fcw, fcb, vf, out);
}

// round 9
// speedup vs baseline: 2.7571x; 2.2909x over previous
#include <cuda_runtime.h>
#include <math.h>
#include <stdint.h>

// ---------------------------------------------------------------------------
// Problem constants
// ---------------------------------------------------------------------------
#define BB   4      // batch
#define CC   64     // C
#define EE   128    // E = 2C
#define HH   128
#define WWID 128
#define WS_  8
#define STR_ 4
#define NH_  31     // windows per dim
#define NWIN (NH_*NH_)          // 961
#define NWB  (NWIN*BB)          // 3844
#define NTOK (NWB*64)           // 246016 token rows
#define HW   (HH*WWID)          // 16384

// ---------------------------------------------------------------------------
// Scratch (static device globals; no runtime allocation)
// ---------------------------------------------------------------------------
__device__ __align__(16) float g_mid [BB*64*HW];          // conv1 out
__device__ __align__(16) float g_nhwc[BB*HW*EE];           // combined0, NHWC
__device__ __align__(16) float g_qkv [(size_t)NTOK*384];
__device__ __align__(16) float g_o2  [(size_t)NTOK*128];
__device__ __align__(16) float g_att [(size_t)NTOK*128];

// ---------------------------------------------------------------------------
// tf32 helpers
// ---------------------------------------------------------------------------
__device__ __forceinline__ uint32_t f2tf(float f) {
    uint32_t u;
    asm("cvt.rna.tf32.f32 %0, %1;" : "=r"(u) : "f"(f));
    return u;
}

__device__ __forceinline__ void mma_tf32(float* d, const uint32_t* a, const uint32_t* b) {
    asm volatile(
        "mma.sync.aligned.m16n8k8.row.col.f32.tf32.tf32.f32 "
        "{%0,%1,%2,%3}, {%4,%5,%6,%7}, {%8,%9}, {%0,%1,%2,%3};\n"
        : "+f"(d[0]), "+f"(d[1]), "+f"(d[2]), "+f"(d[3])
        : "r"(a[0]), "r"(a[1]), "r"(a[2]), "r"(a[3]), "r"(b[0]), "r"(b[1]));
}

// ---------------------------------------------------------------------------
// conv1: 3x3, 64 -> 32 per branch, ReLU.
// ---------------------------------------------------------------------------
__global__ void conv1_kernel(const float* __restrict__ vf,
                             const float* __restrict__ mw1, const float* __restrict__ mb1,
                             const float* __restrict__ aw1, const float* __restrict__ ab1)
{
    int z   = blockIdx.z;            // b*8 + br*4 + ocg
    int b   = z >> 3;
    int br  = (z >> 2) & 1;
    int ocg = z & 3;
    const float* w    = br ? aw1 : mw1;   // [32][64][9]
    const float* bias = br ? ab1 : mb1;
    int ocBase = ocg * 8;
    int x0 = blockIdx.x * 32, y0 = blockIdx.y * 16;
    int tx = threadIdx.x, ty = threadIdx.y;
    int tid = ty * 16 + tx;

    __shared__ float sh[8][18][35];
    __shared__ float wsh[8][8][9];

    float acc[8][2];
#pragma unroll
    for (int o = 0; o < 8; o++) {
        float bv = bias[ocBase + o];
        acc[o][0] = bv; acc[o][1] = bv;
    }

    const float* inBase = vf + (size_t)(b * 128 + br * 64) * HW;

    for (int ic0 = 0; ic0 < 64; ic0 += 8) {
        __syncthreads();
        for (int idx = tid; idx < 8 * 18 * 34; idx += 256) {
            int ic = idx / (18 * 34);
            int r  = idx % (18 * 34);
            int iy = r / 34, ix = r % 34;
            int gy = y0 + iy - 1, gx = x0 + ix - 1;
            float v = 0.f;
            if (gy >= 0 && gy < HH && gx >= 0 && gx < WWID)
                v = inBase[(size_t)(ic0 + ic) * HW + gy * WWID + gx];
            sh[ic][iy][ix] = v;
        }
        for (int idx = tid; idx < 8 * 8 * 9; idx += 256) {
            int o = idx / 72;
            int r = idx % 72;
            int ic = r / 9, k = r % 9;
            wsh[o][ic][k] = w[(ocBase + o) * 576 + (ic0 + ic) * 9 + k];
        }
        __syncthreads();
#pragma unroll
        for (int ic = 0; ic < 8; ic++) {
#pragma unroll
            for (int ky = 0; ky < 3; ky++) {
                float xv[4];
#pragma unroll
                for (int q = 0; q < 4; q++) xv[q] = sh[ic][ty + ky][tx * 2 + q];
#pragma unroll
                for (int kx = 0; kx < 3; kx++) {
#pragma unroll
                    for (int o = 0; o < 8; o++) {
                        float wv = wsh[o][ic][ky * 3 + kx];
                        acc[o][0] += xv[kx]     * wv;
                        acc[o][1] += xv[kx + 1] * wv;
                    }
                }
            }
        }
    }
    int y = y0 + ty, x = x0 + tx * 2;
#pragma unroll
    for (int o = 0; o < 8; o++) {
        float* p = g_mid + (size_t)(b * 64 + br * 32 + ocBase + o) * HW + y * WWID + x;
        p[0] = fmaxf(acc[o][0], 0.f);
        p[1] = fmaxf(acc[o][1], 0.f);
    }
}

// ---------------------------------------------------------------------------
// conv2: 3x3, 32 -> 64 per branch, no ReLU, writes NHWC combined0.
// ---------------------------------------------------------------------------
__global__ void conv2_kernel(const float* __restrict__ mw2, const float* __restrict__ mb2,
                             const float* __restrict__ aw2, const float* __restrict__ ab2)
{
    int z   = blockIdx.z;            // b*16 + br*8 + ocg
    int b   = z >> 4;
    int br  = (z >> 3) & 1;
    int ocg = z & 7;
    const float* w    = br ? aw2 : mw2;   // [64][32][9]
    const float* bias = br ? ab2 : mb2;
    int ocBase = ocg * 8;
    int x0 = blockIdx.x * 32, y0 = blockIdx.y * 16;
    int tx = threadIdx.x, ty = threadIdx.y;
    int tid = ty * 16 + tx;

    __shared__ float sh[8][18][35];
    __shared__ float wsh[8][8][9];

    float acc[8][2];
#pragma unroll
    for (int o = 0; o < 8; o++) {
        float bv = bias[ocBase + o];
        acc[o][0] = bv; acc[o][1] = bv;
    }

    const float* inBase = g_mid + (size_t)(b * 64 + br * 32) * HW;

    for (int ic0 = 0; ic0 < 32; ic0 += 8) {
        __syncthreads();
        for (int idx = tid; idx < 8 * 18 * 34; idx += 256) {
            int ic = idx / (18 * 34);
            int r  = idx % (18 * 34);
            int iy = r / 34, ix = r % 34;
            int gy = y0 + iy - 1, gx = x0 + ix - 1;
            float v = 0.f;
            if (gy >= 0 && gy < HH && gx >= 0 && gx < WWID)
                v = inBase[(size_t)(ic0 + ic) * HW + gy * WWID + gx];
            sh[ic][iy][ix] = v;
        }
        for (int idx = tid; idx < 8 * 8 * 9; idx += 256) {
            int o = idx / 72;
            int r = idx % 72;
            int ic = r / 9, k = r % 9;
            wsh[o][ic][k] = w[(ocBase + o) * 288 + (ic0 + ic) * 9 + k];
        }
        __syncthreads();
#pragma unroll
        for (int ic = 0; ic < 8; ic++) {
#pragma unroll
            for (int ky = 0; ky < 3; ky++) {
                float xv[4];
#pragma unroll
                for (int q = 0; q < 4; q++) xv[q] = sh[ic][ty + ky][tx * 2 + q];
#pragma unroll
                for (int kx = 0; kx < 3; kx++) {
#pragma unroll
                    for (int o = 0; o < 8; o++) {
                        float wv = wsh[o][ic][ky * 3 + kx];
                        acc[o][0] += xv[kx]     * wv;
                        acc[o][1] += xv[kx + 1] * wv;
                    }
                }
            }
        }
    }
    int y = y0 + ty, x = x0 + tx * 2;
    int e0 = br * 64 + ocBase;
#pragma unroll
    for (int px = 0; px < 2; px++) {
        float4 f0 = make_float4(acc[0][px], acc[1][px], acc[2][px], acc[3][px]);
        float4 f1 = make_float4(acc[4][px], acc[5][px], acc[6][px], acc[7][px]);
        float* p = g_nhwc + ((size_t)(b * HH + y) * WWID + (x + px)) * EE + e0;
        reinterpret_cast<float4*>(p)[0] = f0;
        reinterpret_cast<float4*>(p)[1] = f1;
    }
}

// ---------------------------------------------------------------------------
// tf32 tensor-core GEMM: C[M x N] = A[M x 128] * Wt[N x 128]^T + bias.
// BM=128, BN=128, BK=32.  256 threads = 8 warps (2 m x 4 n), warp tile 64x32.
// GATHER=true: A rows gathered from NHWC combined0 (token rows contiguous).
// ---------------------------------------------------------------------------
template<bool GATHER>
__global__ __launch_bounds__(256)
void gemm_tf32_kernel(const float* __restrict__ A, const float* __restrict__ Wt,
                      const float* __restrict__ bias, float* __restrict__ C, int N)
{
    __shared__ uint32_t As[32][136];
    __shared__ uint32_t Bs[32][136];

    int tid  = threadIdx.x;
    int lane = tid & 31;
    int wid  = tid >> 5;
    int wm = wid & 1;
    int wn = wid >> 1;
    int m0 = blockIdx.y * 128;
    int n0 = blockIdx.x * 128;

    float acc[4][4][4];
#pragma unroll
    for (int mt = 0; mt < 4; mt++)
#pragma unroll
        for (int nt = 0; nt < 4; nt++)
#pragma unroll
            for (int r = 0; r < 4; r++) acc[mt][nt][r] = 0.f;

    int q = tid & 7;
    const float* arow[4];
    const float* brow[4];
    int rowIdx[4];
#pragma unroll
    for (int s = 0; s < 4; s++) {
        int row = (tid >> 3) + 32 * s;
        rowIdx[s] = row;
        if (GATHER) {
            int m  = m0 + row;
            int l  = m & 63;
            int wb = m >> 6;
            int b  = wb & 3;
            int win = wb >> 2;
            int hi = win / 31;
            int wi = win - hi * 31;
            int h  = hi * 4 + (l >> 3);
            int wc = wi * 4 + (l & 7);
            arow[s] = g_nhwc + ((size_t)((b * 128 + h) * 128 + wc)) * 128;
        } else {
            arow[s] = A + (size_t)(m0 + row) * 128;
        }
        brow[s] = Wt + (size_t)(n0 + row) * 128;
    }

    for (int k0 = 0; k0 < 128; k0 += 32) {
        __syncthreads();
#pragma unroll
        for (int s = 0; s < 4; s++) {
#pragma unroll
            for (int c = 0; c < 4; c++) {
                int k = q + 8 * c;
                As[k][rowIdx[s]] = f2tf(arow[s][k0 + k]);
                Bs[k][rowIdx[s]] = f2tf(brow[s][k0 + k]);
            }
        }
        __syncthreads();

#pragma unroll
        for (int kk = 0; kk < 4; kk++) {
            int c = lane & 3;
            int g = lane >> 2;
            uint32_t a[4][4], b[4][2];
#pragma unroll
            for (int mt = 0; mt < 4; mt++) {
                int r = wm * 64 + mt * 16 + g;
                a[mt][0] = As[kk * 8 + c    ][r];
                a[mt][1] = As[kk * 8 + c    ][r + 8];
                a[mt][2] = As[kk * 8 + c + 4][r];
                a[mt][3] = As[kk * 8 + c + 4][r + 8];
            }
#pragma unroll
            for (int nt = 0; nt < 4; nt++) {
                int n = wn * 32 + nt * 8 + g;
                b[nt][0] = Bs[kk * 8 + c    ][n];
                b[nt][1] = Bs[kk * 8 + c + 4][n];
            }
#pragma unroll
            for (int mt = 0; mt < 4; mt++)
#pragma unroll
                for (int nt = 0; nt < 4; nt++)
                    mma_tf32(acc[mt][nt], a[mt], b[nt]);
        }
    }

    int g  = lane >> 2;
    int c2 = (lane & 3) * 2;
#pragma unroll
    for (int mt = 0; mt < 4; mt++) {
        int row = m0 + wm * 64 + mt * 16 + g;
#pragma unroll
        for (int nt = 0; nt < 4; nt++) {
            int col = n0 + wn * 32 + nt * 8 + c2;
            float b0 = __ldg(bias + col);
            float b1 = __ldg(bias + col + 1);
            float2 v0 = make_float2(acc[mt][nt][0] + b0, acc[mt][nt][1] + b1);
            float2 v1 = make_float2(acc[mt][nt][2] + b0, acc[mt][nt][3] + b1);
            *reinterpret_cast<float2*>(C + (size_t)row * N + col)       = v0;
            *reinterpret_cast<float2*>(C + (size_t)(row + 8) * N + col) = v1;
        }
    }
}

// ---------------------------------------------------------------------------
// Attention core: one block per (window*batch, head).
// ---------------------------------------------------------------------------
__global__ void attn_kernel()
{
    __shared__ float qs[64][33];
    __shared__ float ks[64][33];
    __shared__ float vs[64][33];
    __shared__ float st[64][65];

    int bx = blockIdx.x;
    int head = bx & 3;
    int wb   = bx >> 2;
    int rowBase = wb * 64;
    int tid = threadIdx.x;
    const float scale = 0.17677669529663687f;  // 1/sqrt(32)

    for (int idx = tid; idx < 64 * 32; idx += 256) {
        int l = idx >> 5, d = idx & 31;
        const float* p = g_qkv + (size_t)(rowBase + l) * 384 + head * 32 + d;
        qs[l][d] = p[0] * scale;
        ks[l][d] = p[128];
        vs[l][d] = p[256];
    }
    __syncthreads();

    {
        int mt = tid & 15, lt = tid >> 4;
        float acc[4][4];
#pragma unroll
        for (int i = 0; i < 4; i++)
#pragma unroll
            for (int j = 0; j < 4; j++) acc[i][j] = 0.f;
#pragma unroll
        for (int d = 0; d < 32; d++) {
            float a[4], bb[4];
#pragma unroll
            for (int i = 0; i < 4; i++) a[i] = qs[lt * 4 + i][d];
#pragma unroll
            for (int j = 0; j < 4; j++) bb[j] = ks[mt + 16 * j][d];
#pragma unroll
            for (int i = 0; i < 4; i++)
#pragma unroll
                for (int j = 0; j < 4; j++) acc[i][j] += a[i] * bb[j];
        }
#pragma unroll
        for (int i = 0; i < 4; i++)
#pragma unroll
            for (int j = 0; j < 4; j++) st[lt * 4 + i][mt + 16 * j] = acc[i][j];
    }
    __syncthreads();

    {
        int row  = tid >> 2;
        int part = tid & 3;
        float mx = -1e30f;
#pragma unroll
        for (int i = 0; i < 16; i++) mx = fmaxf(mx, st[row][part * 16 + i]);
        mx = fmaxf(mx, __shfl_xor_sync(0xffffffffu, mx, 1));
        mx = fmaxf(mx, __shfl_xor_sync(0xffffffffu, mx, 2));
        float s = 0.f;
        float ev[16];
#pragma unroll
        for (int i = 0; i < 16; i++) {
            float e = __expf(st[row][part * 16 + i] - mx);
            ev[i] = e;
            s += e;
        }
        s += __shfl_xor_sync(0xffffffffu, s, 1);
        s += __shfl_xor_sync(0xffffffffu, s, 2);
        float inv = 1.f / s;
#pragma unroll
        for (int i = 0; i < 16; i++) st[row][part * 16 + i] = ev[i] * inv;
    }
    __syncthreads();

    {
        int dt = tid & 15, lt = tid >> 4;
        float acc[4][2];
#pragma unroll
        for (int i = 0; i < 4; i++) { acc[i][0] = 0.f; acc[i][1] = 0.f; }
#pragma unroll 4
        for (int m = 0; m < 64; m++) {
            float a[4];
#pragma unroll
            for (int i = 0; i < 4; i++) a[i] = st[lt * 4 + i][m];
            float b0 = vs[m][dt], b1 = vs[m][dt + 16];
#pragma unroll
            for (int i = 0; i < 4; i++) {
                acc[i][0] += a[i] * b0;
                acc[i][1] += a[i] * b1;
            }
        }
#pragma unroll
        for (int i = 0; i < 4; i++) {
            int l = lt * 4 + i;
            g_o2[(size_t)(rowBase + l) * 128 + head * 32 + dt]      = acc[i][0];
            g_o2[(size_t)(rowBase + l) * 128 + head * 32 + dt + 16] = acc[i][1];
        }
    }
}

// ---------------------------------------------------------------------------
// Blend (analytic scan) + 1x1 conv (smem-staged, conflict-free) + sigmoid gate
// + residual, coalesced NCHW out.
// ---------------------------------------------------------------------------
__global__ void blend_kernel(const float* __restrict__ fcw, const float* __restrict__ fcb,
                             const float* __restrict__ vf, float* __restrict__ out)
{
    __shared__ float enh[32][129];
    __shared__ float fw [32][65];
    __shared__ float fcs[128][76];   // fcw transposed: fcs[e][c]; row 304B (16B-aligned)
    __shared__ float fbs[64];

    int wc = blockIdx.x;     // 0..3
    int h  = blockIdx.y;     // 0..127
    int b  = blockIdx.z;     // 0..3
    int w0 = wc * 32;
    int tid = threadIdx.x;

    // Stage fc weights transposed (coalesced global read)
    for (int idx = tid; idx < 64 * 128; idx += 256) {
        int c = idx >> 7, e = idx & 127;
        fcs[e][c] = fcw[idx];
    }
    if (tid < 64) fbs[tid] = fcb[tid];

    int hiLo = max(0, (h - 4) >> 2);
    int hiHi = min(NH_ - 1, h >> 2);

    // Phase 1: enhanced = sequential-scan-equivalent fold per pixel
    for (int s = 0; s < 16; s++) {
        int idx = tid + s * 256;
        int px = idx >> 7;
        int e  = idx & 127;
        int wpix = w0 + px;
        int wiLo = max(0, (wpix - 4) >> 2);
        int wiHi = min(NH_ - 1, wpix >> 2);

        float val = g_nhwc[((size_t)(b * HH + h) * WWID + wpix) * EE + e];
        for (int hi = hiLo; hi <= hiHi; hi++) {
            int lr = (h - hi * 4) * 8;
            for (int wi = wiLo; wi <= wiHi; wi++) {
                int l = lr + (wpix - wi * 4);
                int row = ((hi * NH_ + wi) * 4 + b) * 64 + l;
                val = val * 0.7f + 0.3f * g_att[(size_t)row * 128 + e];
            }
        }
        enh[px][e] = val;
    }
    __syncthreads();

    // Phase 2: flow weights = sigmoid(fcw @ enh + fcb), smem-only, conflict-free.
    // Thread (px = tid>>3, cg = tid&7) computes c = cg*8 .. cg*8+7.
    {
        int px = tid >> 3;
        int cg = tid & 7;
        float acc[8];
#pragma unroll
        for (int j = 0; j < 8; j++) acc[j] = fbs[cg * 8 + j];
#pragma unroll 4
        for (int e = 0; e < 128; e++) {
            float a = enh[px][e];
            const float4* bp = reinterpret_cast<const float4*>(&fcs[e][cg * 8]);
            float4 b0 = bp[0];
            float4 b1 = bp[1];
            acc[0] += a * b0.x; acc[1] += a * b0.y;
            acc[2] += a * b0.z; acc[3] += a * b0.w;
            acc[4] += a * b1.x; acc[5] += a * b1.y;
            acc[6] += a * b1.z; acc[7] += a * b1.w;
        }
#pragma unroll
        for (int j = 0; j < 8; j++)
            fw[px][cg * 8 + j] = 1.f / (1.f + __expf(-acc[j]));
    }
    __syncthreads();

    // Phase 3: out (NCHW) = enh * gate + vf   (coalesced along w)
    for (int s = 0; s < 16; s++) {
        int idx = tid + s * 256;
        int px = idx & 31;
        int ch = idx >> 5;
        size_t off = ((size_t)(b * 128 + ch) * HH + h) * WWID + w0 + px;
        out[off] = enh[px][ch] * fw[px][ch & 63] + vf[off];
    }
}

// ---------------------------------------------------------------------------
// Launch
// ---------------------------------------------------------------------------
extern "C" void kernel_launch(void* const* d_in, const int* in_sizes, int n_in,
                              void* d_out, int out_size)
{
    const float* vf    = (const float*)d_in[0];
    const float* mw1   = (const float*)d_in[1];
    const float* mb1   = (const float*)d_in[2];
    const float* mw2   = (const float*)d_in[3];
    const float* mb2   = (const float*)d_in[4];
    const float* aw1   = (const float*)d_in[5];
    const float* ab1   = (const float*)d_in[6];
    const float* aw2   = (const float*)d_in[7];
    const float* ab2   = (const float*)d_in[8];
    const float* ipw   = (const float*)d_in[9];   // [384,128]
    const float* ipb   = (const float*)d_in[10];
    const float* opw   = (const float*)d_in[11];  // [128,128]
    const float* opb   = (const float*)d_in[12];
    const float* fcw   = (const float*)d_in[13];  // [64,128]
    const float* fcb   = (const float*)d_in[14];
    float* out = (float*)d_out;

    void *pqkv, *po2, *patt;
    cudaGetSymbolAddress(&pqkv, g_qkv);
    cudaGetSymbolAddress(&po2,  g_o2);
    cudaGetSymbolAddress(&patt, g_att);

    dim3 cblk(16, 16);
    conv1_kernel<<<dim3(4, 8, 32), cblk>>>(vf, mw1, mb1, aw1, ab1);
    conv2_kernel<<<dim3(4, 8, 64), cblk>>>(mw2, mb2, aw2, ab2);

    // QKV: tokens (gathered from NHWC) x [384,128]^T  -> g_qkv
    gemm_tf32_kernel<true><<<dim3(3, NTOK / 128), 256>>>(
        nullptr, ipw, ipb, (float*)pqkv, 384);

    attn_kernel<<<NWB * 4, 256>>>();

    // out-proj: g_o2 [NTOK,128] x [128,128]^T -> g_att
    gemm_tf32_kernel<false><<<dim3(1, NTOK / 128), 256>>>(
        (const float*)po2, opw, opb, (float*)patt, 128);

    blend_kernel<<<dim3(4, HH, BB), 256>>>(fcw, fcb, vf, out);
}

// round 10
// speedup vs baseline: 2.9521x; 1.0707x over previous
#include <cuda_runtime.h>
#include <math.h>
#include <stdint.h>

// ---------------------------------------------------------------------------
// Problem constants
// ---------------------------------------------------------------------------
#define BB   4      // batch
#define CC   64     // C
#define EE   128    // E = 2C
#define HH   128
#define WWID 128
#define WS_  8
#define STR_ 4
#define NH_  31     // windows per dim
#define NWIN (NH_*NH_)          // 961
#define NWB  (NWIN*BB)          // 3844
#define NTOK (NWB*64)           // 246016 token rows
#define HW   (HH*WWID)          // 16384

// ---------------------------------------------------------------------------
// Scratch (static device globals; no runtime allocation)
// ---------------------------------------------------------------------------
__device__ __align__(16) float g_mid [BB*64*HW];          // conv1 out
__device__ __align__(16) float g_nhwc[BB*HW*EE];           // combined0, NHWC
__device__ __align__(16) float g_qkv [(size_t)NTOK*384];
__device__ __align__(16) float g_o2  [(size_t)NTOK*128];
__device__ __align__(16) float g_att [(size_t)NTOK*128];

// ---------------------------------------------------------------------------
// tf32 helpers
// ---------------------------------------------------------------------------
__device__ __forceinline__ uint32_t f2tf(float f) {
    uint32_t u;
    asm("cvt.rna.tf32.f32 %0, %1;" : "=r"(u) : "f"(f));
    return u;
}

__device__ __forceinline__ void mma_tf32(float* d, const uint32_t* a, const uint32_t* b) {
    asm volatile(
        "mma.sync.aligned.m16n8k8.row.col.f32.tf32.tf32.f32 "
        "{%0,%1,%2,%3}, {%4,%5,%6,%7}, {%8,%9}, {%0,%1,%2,%3};\n"
        : "+f"(d[0]), "+f"(d[1]), "+f"(d[2]), "+f"(d[3])
        : "r"(a[0]), "r"(a[1]), "r"(a[2]), "r"(a[3]), "r"(b[0]), "r"(b[1]));
}

// ---------------------------------------------------------------------------
// conv1: 3x3, 64 -> 32 per branch, ReLU.
// ---------------------------------------------------------------------------
__global__ void conv1_kernel(const float* __restrict__ vf,
                             const float* __restrict__ mw1, const float* __restrict__ mb1,
                             const float* __restrict__ aw1, const float* __restrict__ ab1)
{
    int z   = blockIdx.z;            // b*8 + br*4 + ocg
    int b   = z >> 3;
    int br  = (z >> 2) & 1;
    int ocg = z & 3;
    const float* w    = br ? aw1 : mw1;   // [32][64][9]
    const float* bias = br ? ab1 : mb1;
    int ocBase = ocg * 8;
    int x0 = blockIdx.x * 32, y0 = blockIdx.y * 16;
    int tx = threadIdx.x, ty = threadIdx.y;
    int tid = ty * 16 + tx;

    __shared__ float sh[8][18][35];
    __shared__ float wsh[8][8][9];

    float acc[8][2];
#pragma unroll
    for (int o = 0; o < 8; o++) {
        float bv = bias[ocBase + o];
        acc[o][0] = bv; acc[o][1] = bv;
    }

    const float* inBase = vf + (size_t)(b * 128 + br * 64) * HW;

    for (int ic0 = 0; ic0 < 64; ic0 += 8) {
        __syncthreads();
        for (int idx = tid; idx < 8 * 18 * 34; idx += 256) {
            int ic = idx / (18 * 34);
            int r  = idx % (18 * 34);
            int iy = r / 34, ix = r % 34;
            int gy = y0 + iy - 1, gx = x0 + ix - 1;
            float v = 0.f;
            if (gy >= 0 && gy < HH && gx >= 0 && gx < WWID)
                v = inBase[(size_t)(ic0 + ic) * HW + gy * WWID + gx];
            sh[ic][iy][ix] = v;
        }
        for (int idx = tid; idx < 8 * 8 * 9; idx += 256) {
            int o = idx / 72;
            int r = idx % 72;
            int ic = r / 9, k = r % 9;
            wsh[o][ic][k] = w[(ocBase + o) * 576 + (ic0 + ic) * 9 + k];
        }
        __syncthreads();
#pragma unroll
        for (int ic = 0; ic < 8; ic++) {
#pragma unroll
            for (int ky = 0; ky < 3; ky++) {
                float xv[4];
#pragma unroll
                for (int q = 0; q < 4; q++) xv[q] = sh[ic][ty + ky][tx * 2 + q];
#pragma unroll
                for (int kx = 0; kx < 3; kx++) {
#pragma unroll
                    for (int o = 0; o < 8; o++) {
                        float wv = wsh[o][ic][ky * 3 + kx];
                        acc[o][0] += xv[kx]     * wv;
                        acc[o][1] += xv[kx + 1] * wv;
                    }
                }
            }
        }
    }
    int y = y0 + ty, x = x0 + tx * 2;
#pragma unroll
    for (int o = 0; o < 8; o++) {
        float* p = g_mid + (size_t)(b * 64 + br * 32 + ocBase + o) * HW + y * WWID + x;
        p[0] = fmaxf(acc[o][0], 0.f);
        p[1] = fmaxf(acc[o][1], 0.f);
    }
}

// ---------------------------------------------------------------------------
// conv2: 3x3, 32 -> 64 per branch, no ReLU, writes NHWC combined0.
// ---------------------------------------------------------------------------
__global__ void conv2_kernel(const float* __restrict__ mw2, const float* __restrict__ mb2,
                             const float* __restrict__ aw2, const float* __restrict__ ab2)
{
    int z   = blockIdx.z;            // b*16 + br*8 + ocg
    int b   = z >> 4;
    int br  = (z >> 3) & 1;
    int ocg = z & 7;
    const float* w    = br ? aw2 : mw2;   // [64][32][9]
    const float* bias = br ? ab2 : mb2;
    int ocBase = ocg * 8;
    int x0 = blockIdx.x * 32, y0 = blockIdx.y * 16;
    int tx = threadIdx.x, ty = threadIdx.y;
    int tid = ty * 16 + tx;

    __shared__ float sh[8][18][35];
    __shared__ float wsh[8][8][9];

    float acc[8][2];
#pragma unroll
    for (int o = 0; o < 8; o++) {
        float bv = bias[ocBase + o];
        acc[o][0] = bv; acc[o][1] = bv;
    }

    const float* inBase = g_mid + (size_t)(b * 64 + br * 32) * HW;

    for (int ic0 = 0; ic0 < 32; ic0 += 8) {
        __syncthreads();
        for (int idx = tid; idx < 8 * 18 * 34; idx += 256) {
            int ic = idx / (18 * 34);
            int r  = idx % (18 * 34);
            int iy = r / 34, ix = r % 34;
            int gy = y0 + iy - 1, gx = x0 + ix - 1;
            float v = 0.f;
            if (gy >= 0 && gy < HH && gx >= 0 && gx < WWID)
                v = inBase[(size_t)(ic0 + ic) * HW + gy * WWID + gx];
            sh[ic][iy][ix] = v;
        }
        for (int idx = tid; idx < 8 * 8 * 9; idx += 256) {
            int o = idx / 72;
            int r = idx % 72;
            int ic = r / 9, k = r % 9;
            wsh[o][ic][k] = w[(ocBase + o) * 288 + (ic0 + ic) * 9 + k];
        }
        __syncthreads();
#pragma unroll
        for (int ic = 0; ic < 8; ic++) {
#pragma unroll
            for (int ky = 0; ky < 3; ky++) {
                float xv[4];
#pragma unroll
                for (int q = 0; q < 4; q++) xv[q] = sh[ic][ty + ky][tx * 2 + q];
#pragma unroll
                for (int kx = 0; kx < 3; kx++) {
#pragma unroll
                    for (int o = 0; o < 8; o++) {
                        float wv = wsh[o][ic][ky * 3 + kx];
                        acc[o][0] += xv[kx]     * wv;
                        acc[o][1] += xv[kx + 1] * wv;
                    }
                }
            }
        }
    }
    int y = y0 + ty, x = x0 + tx * 2;
    int e0 = br * 64 + ocBase;
#pragma unroll
    for (int px = 0; px < 2; px++) {
        float4 f0 = make_float4(acc[0][px], acc[1][px], acc[2][px], acc[3][px]);
        float4 f1 = make_float4(acc[4][px], acc[5][px], acc[6][px], acc[7][px]);
        float* p = g_nhwc + ((size_t)(b * HH + y) * WWID + (x + px)) * EE + e0;
        reinterpret_cast<float4*>(p)[0] = f0;
        reinterpret_cast<float4*>(p)[1] = f1;
    }
}

// ---------------------------------------------------------------------------
// tf32 tensor-core GEMM: C[M x N] = A[M x 128] * Wt[N x 128]^T + bias.
// ---------------------------------------------------------------------------
template<bool GATHER>
__global__ __launch_bounds__(256)
void gemm_tf32_kernel(const float* __restrict__ A, const float* __restrict__ Wt,
                      const float* __restrict__ bias, float* __restrict__ C, int N)
{
    __shared__ uint32_t As[32][136];
    __shared__ uint32_t Bs[32][136];

    int tid  = threadIdx.x;
    int lane = tid & 31;
    int wid  = tid >> 5;
    int wm = wid & 1;
    int wn = wid >> 1;
    int m0 = blockIdx.y * 128;
    int n0 = blockIdx.x * 128;

    float acc[4][4][4];
#pragma unroll
    for (int mt = 0; mt < 4; mt++)
#pragma unroll
        for (int nt = 0; nt < 4; nt++)
#pragma unroll
            for (int r = 0; r < 4; r++) acc[mt][nt][r] = 0.f;

    int q = tid & 7;
    const float* arow[4];
    const float* brow[4];
    int rowIdx[4];
#pragma unroll
    for (int s = 0; s < 4; s++) {
        int row = (tid >> 3) + 32 * s;
        rowIdx[s] = row;
        if (GATHER) {
            int m  = m0 + row;
            int l  = m & 63;
            int wb = m >> 6;
            int b  = wb & 3;
            int win = wb >> 2;
            int hi = win / 31;
            int wi = win - hi * 31;
            int h  = hi * 4 + (l >> 3);
            int wc = wi * 4 + (l & 7);
            arow[s] = g_nhwc + ((size_t)((b * 128 + h) * 128 + wc)) * 128;
        } else {
            arow[s] = A + (size_t)(m0 + row) * 128;
        }
        brow[s] = Wt + (size_t)(n0 + row) * 128;
    }

    for (int k0 = 0; k0 < 128; k0 += 32) {
        __syncthreads();
#pragma unroll
        for (int s = 0; s < 4; s++) {
#pragma unroll
            for (int c = 0; c < 4; c++) {
                int k = q + 8 * c;
                As[k][rowIdx[s]] = f2tf(arow[s][k0 + k]);
                Bs[k][rowIdx[s]] = f2tf(brow[s][k0 + k]);
            }
        }
        __syncthreads();

#pragma unroll
        for (int kk = 0; kk < 4; kk++) {
            int c = lane & 3;
            int g = lane >> 2;
            uint32_t a[4][4], b[4][2];
#pragma unroll
            for (int mt = 0; mt < 4; mt++) {
                int r = wm * 64 + mt * 16 + g;
                a[mt][0] = As[kk * 8 + c    ][r];
                a[mt][1] = As[kk * 8 + c    ][r + 8];
                a[mt][2] = As[kk * 8 + c + 4][r];
                a[mt][3] = As[kk * 8 + c + 4][r + 8];
            }
#pragma unroll
            for (int nt = 0; nt < 4; nt++) {
                int n = wn * 32 + nt * 8 + g;
                b[nt][0] = Bs[kk * 8 + c    ][n];
                b[nt][1] = Bs[kk * 8 + c + 4][n];
            }
#pragma unroll
            for (int mt = 0; mt < 4; mt++)
#pragma unroll
                for (int nt = 0; nt < 4; nt++)
                    mma_tf32(acc[mt][nt], a[mt], b[nt]);
        }
    }

    int g  = lane >> 2;
    int c2 = (lane & 3) * 2;
#pragma unroll
    for (int mt = 0; mt < 4; mt++) {
        int row = m0 + wm * 64 + mt * 16 + g;
#pragma unroll
        for (int nt = 0; nt < 4; nt++) {
            int col = n0 + wn * 32 + nt * 8 + c2;
            float b0 = __ldg(bias + col);
            float b1 = __ldg(bias + col + 1);
            float2 v0 = make_float2(acc[mt][nt][0] + b0, acc[mt][nt][1] + b1);
            float2 v1 = make_float2(acc[mt][nt][2] + b0, acc[mt][nt][3] + b1);
            *reinterpret_cast<float2*>(C + (size_t)row * N + col)       = v0;
            *reinterpret_cast<float2*>(C + (size_t)(row + 8) * N + col) = v1;
        }
    }
}

// ---------------------------------------------------------------------------
// Attention core (tensor cores): one block (128 thr) per (window*batch, head).
// S = Q K^T via mma tf32, softmax, O = P V via mma tf32.
// Layouts: qsT[d][l], ksT[d][m] (pad 72), vs[m][d] (pad 40),
//          st[m][l] (pad 68) — S stored transposed so it is directly the
//          A-operand smem layout (As[k=m][row=l]) for the PV mma.
// ---------------------------------------------------------------------------
__global__ __launch_bounds__(128)
void attn_kernel()
{
    __shared__ uint32_t qsT[32][72];
    __shared__ uint32_t ksT[32][72];
    __shared__ uint32_t vs [64][40];
    __shared__ float    st [64][68];
    __shared__ float    smx[128];
    __shared__ float    ssum[128];

    int bx   = blockIdx.x;
    int head = bx & 3;
    int wb   = bx >> 2;
    int rowBase = wb * 64;
    int tid  = threadIdx.x;
    int lane = tid & 31;
    int warp = tid >> 5;
    const float scale = 0.17677669529663687f;  // 1/sqrt(32)

    // ---- load Q,K,V (each thread: one l-row, 16 d's) ----
    {
        int l     = tid & 63;
        int dbase = (tid >> 6) * 16;
        const float* p = g_qkv + (size_t)(rowBase + l) * 384 + head * 32 + dbase;
#pragma unroll
        for (int j4 = 0; j4 < 4; j4++) {
            float4 qv = *reinterpret_cast<const float4*>(p + j4 * 4);
            float4 kv = *reinterpret_cast<const float4*>(p + 128 + j4 * 4);
            float4 vv = *reinterpret_cast<const float4*>(p + 256 + j4 * 4);
            int d = dbase + j4 * 4;
            qsT[d + 0][l] = f2tf(qv.x * scale);
            qsT[d + 1][l] = f2tf(qv.y * scale);
            qsT[d + 2][l] = f2tf(qv.z * scale);
            qsT[d + 3][l] = f2tf(qv.w * scale);
            ksT[d + 0][l] = f2tf(kv.x);
            ksT[d + 1][l] = f2tf(kv.y);
            ksT[d + 2][l] = f2tf(kv.z);
            ksT[d + 3][l] = f2tf(kv.w);
            uint4 vt;
            vt.x = f2tf(vv.x); vt.y = f2tf(vv.y);
            vt.z = f2tf(vv.z); vt.w = f2tf(vv.w);
            *reinterpret_cast<uint4*>(&vs[l][d]) = vt;
        }
    }
    __syncthreads();

    int g = lane >> 2, c = lane & 3;
    int lbase = warp * 16;

    // ---- S = Q K^T : M=64(l), N=64(m), K=32(d); warp: 16 l x 64 m ----
    {
        float sacc[8][4];
#pragma unroll
        for (int nt = 0; nt < 8; nt++)
#pragma unroll
            for (int r = 0; r < 4; r++) sacc[nt][r] = 0.f;

#pragma unroll
        for (int kk = 0; kk < 4; kk++) {
            uint32_t a[4];
            a[0] = qsT[kk * 8 + c    ][lbase + g];
            a[1] = qsT[kk * 8 + c    ][lbase + g + 8];
            a[2] = qsT[kk * 8 + c + 4][lbase + g];
            a[3] = qsT[kk * 8 + c + 4][lbase + g + 8];
#pragma unroll
            for (int nt = 0; nt < 8; nt++) {
                uint32_t b[2];
                b[0] = ksT[kk * 8 + c    ][nt * 8 + g];
                b[1] = ksT[kk * 8 + c + 4][nt * 8 + g];
                mma_tf32(sacc[nt], a, b);
            }
        }
        // store transposed: st[m][l]
#pragma unroll
        for (int nt = 0; nt < 8; nt++) {
            int m = nt * 8 + c * 2;
            st[m    ][lbase + g]     = sacc[nt][0];
            st[m + 1][lbase + g]     = sacc[nt][1];
            st[m    ][lbase + g + 8] = sacc[nt][2];
            st[m + 1][lbase + g + 8] = sacc[nt][3];
        }
    }
    __syncthreads();

    // ---- softmax over m per column l; 2 threads per l (32 m each) ----
    {
        int l     = tid & 63;
        int part  = tid >> 6;
        int mbase = part * 32;
        float mx = -1e30f;
#pragma unroll
        for (int i = 0; i < 32; i++) mx = fmaxf(mx, st[mbase + i][l]);
        smx[part * 64 + l] = mx;
        __syncthreads();
        mx = fmaxf(smx[l], smx[64 + l]);
        float s = 0.f;
        float ev[32];
#pragma unroll
        for (int i = 0; i < 32; i++) {
            float e = __expf(st[mbase + i][l] - mx);
            ev[i] = e;
            s += e;
        }
        ssum[part * 64 + l] = s;
        __syncthreads();
        float inv = 1.f / (ssum[l] + ssum[64 + l]);
#pragma unroll
        for (int i = 0; i < 32; i++)
            st[mbase + i][l] = __uint_as_float(f2tf(ev[i] * inv));
    }
    __syncthreads();

    // ---- O = P V : M=64(l), N=32(d), K=64(m); warp: 16 l x 32 d ----
    {
        float oacc[4][4];
#pragma unroll
        for (int nt = 0; nt < 4; nt++)
#pragma unroll
            for (int r = 0; r < 4; r++) oacc[nt][r] = 0.f;

#pragma unroll
        for (int kk = 0; kk < 8; kk++) {
            uint32_t a[4];
            a[0] = __float_as_uint(st[kk * 8 + c    ][lbase + g]);
            a[1] = __float_as_uint(st[kk * 8 + c    ][lbase + g + 8]);
            a[2] = __float_as_uint(st[kk * 8 + c + 4][lbase + g]);
            a[3] = __float_as_uint(st[kk * 8 + c + 4][lbase + g + 8]);
#pragma unroll
            for (int nt = 0; nt < 4; nt++) {
                uint32_t b[2];
                b[0] = vs[kk * 8 + c    ][nt * 8 + g];
                b[1] = vs[kk * 8 + c + 4][nt * 8 + g];
                mma_tf32(oacc[nt], a, b);
            }
        }
        // write g_o2[(rowBase+l)*128 + head*32 + d]
        int c2 = c * 2;
#pragma unroll
        for (int nt = 0; nt < 4; nt++) {
            int d = head * 32 + nt * 8 + c2;
            float2 v0 = make_float2(oacc[nt][0], oacc[nt][1]);
            float2 v1 = make_float2(oacc[nt][2], oacc[nt][3]);
            *reinterpret_cast<float2*>(g_o2 + (size_t)(rowBase + lbase + g) * 128 + d)     = v0;
            *reinterpret_cast<float2*>(g_o2 + (size_t)(rowBase + lbase + g + 8) * 128 + d) = v1;
        }
    }
}

// ---------------------------------------------------------------------------
// Blend (analytic scan) + 1x1 conv (smem-staged) + sigmoid gate + residual.
// ---------------------------------------------------------------------------
__global__ void blend_kernel(const float* __restrict__ fcw, const float* __restrict__ fcb,
                             const float* __restrict__ vf, float* __restrict__ out)
{
    __shared__ float enh[32][129];
    __shared__ float fw [32][65];
    __shared__ float fcs[128][76];
    __shared__ float fbs[64];

    int wc = blockIdx.x;     // 0..3
    int h  = blockIdx.y;     // 0..127
    int b  = blockIdx.z;     // 0..3
    int w0 = wc * 32;
    int tid = threadIdx.x;

    for (int idx = tid; idx < 64 * 128; idx += 256) {
        int c = idx >> 7, e = idx & 127;
        fcs[e][c] = fcw[idx];
    }
    if (tid < 64) fbs[tid] = fcb[tid];

    int hiLo = max(0, (h - 4) >> 2);
    int hiHi = min(NH_ - 1, h >> 2);

    for (int s = 0; s < 16; s++) {
        int idx = tid + s * 256;
        int px = idx >> 7;
        int e  = idx & 127;
        int wpix = w0 + px;
        int wiLo = max(0, (wpix - 4) >> 2);
        int wiHi = min(NH_ - 1, wpix >> 2);

        float val = g_nhwc[((size_t)(b * HH + h) * WWID + wpix) * EE + e];
        for (int hi = hiLo; hi <= hiHi; hi++) {
            int lr = (h - hi * 4) * 8;
            for (int wi = wiLo; wi <= wiHi; wi++) {
                int l = lr + (wpix - wi * 4);
                int row = ((hi * NH_ + wi) * 4 + b) * 64 + l;
                val = val * 0.7f + 0.3f * g_att[(size_t)row * 128 + e];
            }
        }
        enh[px][e] = val;
    }
    __syncthreads();

    {
        int px = tid >> 3;
        int cg = tid & 7;
        float acc[8];
#pragma unroll
        for (int j = 0; j < 8; j++) acc[j] = fbs[cg * 8 + j];
#pragma unroll 4
        for (int e = 0; e < 128; e++) {
            float a = enh[px][e];
            const float4* bp = reinterpret_cast<const float4*>(&fcs[e][cg * 8]);
            float4 b0 = bp[0];
            float4 b1 = bp[1];
            acc[0] += a * b0.x; acc[1] += a * b0.y;
            acc[2] += a * b0.z; acc[3] += a * b0.w;
            acc[4] += a * b1.x; acc[5] += a * b1.y;
            acc[6] += a * b1.z; acc[7] += a * b1.w;
        }
#pragma unroll
        for (int j = 0; j < 8; j++)
            fw[px][cg * 8 + j] = 1.f / (1.f + __expf(-acc[j]));
    }
    __syncthreads();

    for (int s = 0; s < 16; s++) {
        int idx = tid + s * 256;
        int px = idx & 31;
        int ch = idx >> 5;
        size_t off = ((size_t)(b * 128 + ch) * HH + h) * WWID + w0 + px;
        out[off] = enh[px][ch] * fw[px][ch & 63] + vf[off];
    }
}

// ---------------------------------------------------------------------------
// Launch
// ---------------------------------------------------------------------------
extern "C" void kernel_launch(void* const* d_in, const int* in_sizes, int n_in,
                              void* d_out, int out_size)
{
    const float* vf    = (const float*)d_in[0];
    const float* mw1   = (const float*)d_in[1];
    const float* mb1   = (const float*)d_in[2];
    const float* mw2   = (const float*)d_in[3];
    const float* mb2   = (const float*)d_in[4];
    const float* aw1   = (const float*)d_in[5];
    const float* ab1   = (const float*)d_in[6];
    const float* aw2   = (const float*)d_in[7];
    const float* ab2   = (const float*)d_in[8];
    const float* ipw   = (const float*)d_in[9];   // [384,128]
    const float* ipb   = (const float*)d_in[10];
    const float* opw   = (const float*)d_in[11];  // [128,128]
    const float* opb   = (const float*)d_in[12];
    const float* fcw   = (const float*)d_in[13];  // [64,128]
    const float* fcb   = (const float*)d_in[14];
    float* out = (float*)d_out;

    void *pqkv, *po2, *patt;
    cudaGetSymbolAddress(&pqkv, g_qkv);
    cudaGetSymbolAddress(&po2,  g_o2);
    cudaGetSymbolAddress(&patt, g_att);

    dim3 cblk(16, 16);
    conv1_kernel<<<dim3(4, 8, 32), cblk>>>(vf, mw1, mb1, aw1, ab1);
    conv2_kernel<<<dim3(4, 8, 64), cblk>>>(mw2, mb2, aw2, ab2);

    // QKV: tokens (gathered from NHWC) x [384,128]^T  -> g_qkv
    gemm_tf32_kernel<true><<<dim3(3, NTOK / 128), 256>>>(
        nullptr, ipw, ipb, (float*)pqkv, 384);

    attn_kernel<<<NWB * 4, 128>>>();

    // out-proj: g_o2 [NTOK,128] x [128,128]^T -> g_att
    gemm_tf32_kernel<false><<<dim3(1, NTOK / 128), 256>>>(
        (const float*)po2, opw, opb, (float*)patt, 128);

    blend_kernel<<<dim3(4, HH, BB), 256>>>(fcw, fcb, vf, out);
}